// round 1
// baseline (speedup 1.0000x reference)
#include <cuda_runtime.h>
#include <math.h>

#define Bn  64
#define Tn  128
#define En  300
#define Hn  256
#define G4  1024
#define G2  512
#define FHn 256

// ---------------- device scratch (no cudaMalloc allowed) ----------------
__device__ float g_xproj[2][(size_t)Bn*Tn*G4];   // 64 MB: per-dir x@W_ih^T + biases
__device__ float g_hbuf[2][2][Hn*Bn];            // [dir][parity][u*64+b]
__device__ float g_pooled[Bn*G2];
__device__ float g_gat[Bn*G2];
__device__ float g_x1[Bn*FHn];
__device__ float g_x2[Bn*FHn];
__device__ unsigned g_bar_count = 0;
__device__ unsigned g_bar_gen   = 0;

// ---------------- kernel 1: gathered input projection GEMM ----------------
// out[dir][(b*T+t)*1024 + j] = emb[sent[b,t]] . w_ih[dir][j] + b_ih[j] + b_hh[j]
// Tiles: 128 rows x 64 cols, K staged in chunks of 32.
__global__ void proj_kernel(const int* __restrict__ sentence,
                            const float* __restrict__ emb,
                            const float* __restrict__ wf, const float* __restrict__ wb,
                            const float* __restrict__ bihf, const float* __restrict__ bhhf,
                            const float* __restrict__ bihb, const float* __restrict__ bhhb)
{
    __shared__ float Asm[128][33];
    __shared__ float Bsm[64][33];
    __shared__ int   tok_sm[128];
    int tid = threadIdx.x;
    int rowbase = blockIdx.y * 128;
    int colbase = blockIdx.x * 64;          // cols 0..2047, dir uniform per block
    int dir = colbase >> 10;
    const float* wsrc = dir ? wb : wf;
    if (tid < 128) tok_sm[tid] = sentence[rowbase + tid];
    __syncthreads();

    int tx = tid & 15, ty = tid >> 4;
    float acc[8][4];
    #pragma unroll
    for (int i = 0; i < 8; i++)
        #pragma unroll
        for (int j = 0; j < 4; j++) acc[i][j] = 0.f;

    for (int k0 = 0; k0 < 320; k0 += 32) {
        #pragma unroll
        for (int it = 0; it < 16; ++it) {          // stage A (gathered emb rows)
            int idx = tid + it * 256;
            int kk = idx & 31, r = idx >> 5;
            int k = k0 + kk;
            Asm[r][kk] = (k < En) ? emb[(size_t)tok_sm[r] * En + k] : 0.f;
        }
        #pragma unroll
        for (int it = 0; it < 8; ++it) {           // stage B (w_ih slice)
            int idx = tid + it * 256;
            int kk = idx & 31, r = idx >> 5;
            int k = k0 + kk;
            int jg = (colbase + r) & 1023;
            Bsm[r][kk] = (k < En) ? wsrc[jg * En + k] : 0.f;
        }
        __syncthreads();
        #pragma unroll
        for (int kk = 0; kk < 32; ++kk) {
            float a[8], bb[4];
            #pragma unroll
            for (int i = 0; i < 8; i++) a[i] = Asm[ty*8 + i][kk];
            #pragma unroll
            for (int j = 0; j < 4; j++) bb[j] = Bsm[tx*4 + j][kk];
            #pragma unroll
            for (int i = 0; i < 8; i++)
                #pragma unroll
                for (int j = 0; j < 4; j++) acc[i][j] += a[i] * bb[j];
        }
        __syncthreads();
    }
    const float* bih = dir ? bihb : bihf;
    const float* bhh = dir ? bhhb : bhhf;
    float* outp = g_xproj[dir];
    #pragma unroll
    for (int i = 0; i < 8; i++) {
        int row = rowbase + ty*8 + i;
        #pragma unroll
        for (int j = 0; j < 4; j++) {
            int jg = (colbase + tx*4 + j) & 1023;
            outp[(size_t)row * G4 + jg] = acc[i][j] + bih[jg] + bhh[jg];
        }
    }
}

// ---------------- grid barrier (persistent, 128 blocks <= 148 SMs) ----------------
// epoch is launch-relative (base read before any release can occur), so CUDA-graph
// replays are deterministic even though g_bar_gen keeps counting across launches.
__device__ __forceinline__ void grid_barrier(unsigned nb, unsigned base, unsigned epoch)
{
    __syncthreads();
    if (threadIdx.x == 0) {
        __threadfence();
        if (atomicAdd(&g_bar_count, 1u) == nb - 1u) {
            g_bar_count = 0;
            __threadfence();
            atomicAdd(&g_bar_gen, 1u);
        } else {
            while (((*(volatile unsigned*)&g_bar_gen) - base) < epoch) __nanosleep(64);
        }
    }
    __syncthreads();
}

// ---------------- kernel 2: BiLSTM recurrence + masked pooled sum ----------------
// 128 blocks: dir = blk>>6, 4 hidden units per block, 256 threads = (b:64, uloc:4).
// w_hh slice (16 rows x 256) in SMEM; h staged k-major [k][b] in SMEM each step.
__global__ void recur_kernel(const float* __restrict__ whh_f,
                             const float* __restrict__ whh_b,
                             const int* __restrict__ text_len)
{
    extern __shared__ float dyn[];
    float* h_sm = dyn;                 // 256*64 floats
    float* w_sm = dyn + Hn * Bn;       // 4*4*256 floats: [gate][uloc][k]

    int dir = blockIdx.x >> 6;
    int ub  = blockIdx.x & 63;
    int tid = threadIdx.x;
    int b = tid & 63, uloc = tid >> 6;
    int u = ub * 4 + uloc;

    __shared__ unsigned s_base;
    if (tid == 0) s_base = *(volatile unsigned*)&g_bar_gen;

    const float* whh = dir ? whh_b : whh_f;
    for (int idx = tid; idx < 4*4*Hn; idx += 256) {
        int k  = idx & 255;
        int ul = (idx >> 8) & 3;
        int g  = idx >> 10;
        w_sm[idx] = whh[((size_t)(g*Hn + ub*4 + ul)) * Hn + k];
    }
    __syncthreads();
    unsigned base = s_base;

    const float* wg0 = &w_sm[(0*4 + uloc) * Hn];
    const float* wg1 = &w_sm[(1*4 + uloc) * Hn];
    const float* wg2 = &w_sm[(2*4 + uloc) * Hn];
    const float* wg3 = &w_sm[(3*4 + uloc) * Hn];
    const float* xp = g_xproj[dir];

    float c = 0.f, pooled = 0.f;
    int len = text_len[b];

    for (int step = 0; step < Tn; ++step) {
        int tpos = dir ? (Tn - 1 - step) : step;
        const float* xr = xp + (size_t)(b * Tn + tpos) * G4;
        float g0 = xr[u], g1 = xr[Hn + u], g2 = xr[2*Hn + u], g3 = xr[3*Hn + u];

        if (step > 0) {
            const float* hsrc = g_hbuf[dir][(step + 1) & 1];
            for (int i = tid * 4; i < Hn * Bn; i += 1024)
                *(float4*)(h_sm + i) = *(const float4*)(hsrc + i);
            __syncthreads();
            #pragma unroll 4
            for (int k = 0; k < Hn; k += 4) {
                float4 w0 = *(const float4*)(wg0 + k);
                float4 w1 = *(const float4*)(wg1 + k);
                float4 w2 = *(const float4*)(wg2 + k);
                float4 w3 = *(const float4*)(wg3 + k);
                float h0 = h_sm[(k+0)*Bn + b];
                float h1 = h_sm[(k+1)*Bn + b];
                float h2 = h_sm[(k+2)*Bn + b];
                float h3 = h_sm[(k+3)*Bn + b];
                g0 += w0.x*h0 + w0.y*h1 + w0.z*h2 + w0.w*h3;
                g1 += w1.x*h0 + w1.y*h1 + w1.z*h2 + w1.w*h3;
                g2 += w2.x*h0 + w2.y*h1 + w2.z*h2 + w2.w*h3;
                g3 += w3.x*h0 + w3.y*h1 + w3.z*h2 + w3.w*h3;
            }
        }
        float ig = 1.f / (1.f + __expf(-g0));
        float fg = 1.f / (1.f + __expf(-g1));
        float gg = tanhf(g2);
        float og = 1.f / (1.f + __expf(-g3));
        c = fg * c + ig * gg;
        float h = og * tanhf(c);

        g_hbuf[dir][step & 1][u * Bn + b] = h;
        if (tpos < len) pooled += h;
        grid_barrier(gridDim.x, base, (unsigned)(step + 1));
    }
    g_pooled[b * G2 + dir * Hn + u] = pooled;
}

// ---------------- kernel 3: generic dense head (warp-per-output GEMV) ----------------
__global__ void dense_kernel(const float* __restrict__ in, const float* __restrict__ W,
                             const float* __restrict__ bias, const int* __restrict__ lenp,
                             float* __restrict__ out, int K, int N, int dorelu)
{
    __shared__ float x_sm[512];
    int b = blockIdx.x;
    int tid = threadIdx.x;
    for (int k = tid; k < K; k += blockDim.x) x_sm[k] = in[b * K + k];
    __syncthreads();
    float lenscale = lenp ? (float)lenp[b] : 1.f;
    int lane = tid & 31, warp = tid >> 5;
    int nwarp = blockDim.x >> 5;
    for (int j = warp; j < N; j += nwarp) {
        float acc = 0.f;
        for (int k = lane; k < K; k += 32) acc += W[j * K + k] * x_sm[k];
        #pragma unroll
        for (int off = 16; off; off >>= 1) acc += __shfl_down_sync(0xffffffffu, acc, off);
        if (lane == 0) {
            float v = acc + bias[j] * lenscale;
            if (dorelu) v = fmaxf(v, 0.f);
            out[b * N + j] = v;
        }
    }
}

// ---------------- host entry ----------------
extern "C" void kernel_launch(void* const* d_in, const int* in_sizes, int n_in,
                              void* d_out, int out_size)
{
    const int*   sentence = (const int*)d_in[0];
    const int*   text_len = (const int*)d_in[4];
    const float* emb  = (const float*)d_in[10];
    const float* wihf = (const float*)d_in[11];
    const float* whhf = (const float*)d_in[12];
    const float* bihf = (const float*)d_in[13];
    const float* bhhf = (const float*)d_in[14];
    const float* wihb = (const float*)d_in[15];
    const float* whhb = (const float*)d_in[16];
    const float* bihb = (const float*)d_in[17];
    const float* bhhb = (const float*)d_in[18];
    const float* gatw = (const float*)d_in[19];
    const float* gatb = (const float*)d_in[20];
    const float* fc1w = (const float*)d_in[21];
    const float* fc1b = (const float*)d_in[22];
    const float* fc2w = (const float*)d_in[23];
    const float* fc2b = (const float*)d_in[24];
    const float* fcfw = (const float*)d_in[25];
    const float* fcfb = (const float*)d_in[26];
    float* out = (float*)d_out;

    size_t dynsz = (size_t)(Hn * Bn + 4 * 4 * Hn) * sizeof(float);  // 80 KB
    cudaFuncSetAttribute(recur_kernel, cudaFuncAttributeMaxDynamicSharedMemorySize, (int)dynsz);

    void *p_pooled, *p_gat, *p_x1, *p_x2;
    cudaGetSymbolAddress(&p_pooled, g_pooled);
    cudaGetSymbolAddress(&p_gat, g_gat);
    cudaGetSymbolAddress(&p_x1, g_x1);
    cudaGetSymbolAddress(&p_x2, g_x2);

    proj_kernel<<<dim3(32, 64), 256>>>(sentence, emb, wihf, wihb, bihf, bhhf, bihb, bhhb);
    recur_kernel<<<128, 256, dynsz>>>(whhf, whhb, text_len);
    dense_kernel<<<64, 256>>>((const float*)p_pooled, gatw, gatb, text_len, (float*)p_gat, 512, 512, 1);
    dense_kernel<<<64, 256>>>((const float*)p_gat,  fc1w, fc1b, nullptr, (float*)p_x1, 512, 256, 1);
    dense_kernel<<<64, 256>>>((const float*)p_x1,   fc2w, fc2b, nullptr, (float*)p_x2, 256, 256, 1);
    dense_kernel<<<64, 64>>> ((const float*)p_x2,   fcfw, fcfb, nullptr, out, 256, 2, 0);
}

// round 2
// speedup vs baseline: 1.3095x; 1.3095x over previous
#include <cuda_runtime.h>
#include <math.h>

typedef unsigned long long ull;

#define Bn  64
#define Tn  128
#define En  300
#define Hn  256
#define G4  1024
#define G2  512
#define FHn 256

// ---------------- device scratch ----------------
__device__ float g_xproj[2][(size_t)Bn*Tn*G4];   // [dir][(b*T+t)*1024 + g*256 + u]
__device__ float g_hbuf[2][2][Bn*Hn];            // [dir][parity][b*256 + u]  (b-major)
__device__ float g_pooled[Bn*G2];
__device__ unsigned g_cnt[2];

// ---------------- packed f32x2 helpers ----------------
__device__ __forceinline__ void fma2(ull& d, ull a, ull b){
    asm("fma.rn.f32x2 %0, %1, %2, %0;" : "+l"(d) : "l"(a), "l"(b));
}
__device__ __forceinline__ float hadd2(ull v){
    float a, b;
    asm("mov.b64 {%0, %1}, %2;" : "=f"(a), "=f"(b) : "l"(v));
    return a + b;
}
__device__ __forceinline__ void ldsv2(ull& a, ull& b, unsigned addr){
    asm volatile("ld.shared.v2.b64 {%0, %1}, [%2];" : "=l"(a), "=l"(b) : "r"(addr));
}

// ---------------- kernel 0: barrier reset ----------------
__global__ void reset_kernel(){
    if (threadIdx.x < 2) g_cnt[threadIdx.x] = 0u;
}

// ---------------- kernel 1: gathered input projection GEMM (f32x2) ----------------
// Tile 128 rows x 64 cols, K chunks of 32, micro 8x4, acc paired over K.
__global__ void __launch_bounds__(256,2) proj_kernel(
    const int* __restrict__ sentence, const float* __restrict__ emb,
    const float* __restrict__ wf, const float* __restrict__ wb,
    const float* __restrict__ bihf, const float* __restrict__ bhhf,
    const float* __restrict__ bihb, const float* __restrict__ bhhb)
{
    __shared__ __align__(16) float Asm[128*34];
    __shared__ __align__(16) float Bsm[64*34];
    __shared__ int tok[128];
    int tid = threadIdx.x;
    int rowbase = blockIdx.y * 128;
    int colbase = blockIdx.x * 64;          // 0..2047; dir uniform per block
    int dir = colbase >> 10;
    const float* wsrc = dir ? wb : wf;
    if (tid < 128) tok[tid] = sentence[rowbase + tid];
    __syncthreads();

    int tx = tid & 15, ty = tid >> 4;
    ull acc[8][4];
    #pragma unroll
    for (int i = 0; i < 8; i++)
        #pragma unroll
        for (int j = 0; j < 4; j++) acc[i][j] = 0ull;

    for (int k0 = 0; k0 < 320; k0 += 32) {
        #pragma unroll
        for (int it = 0; it < 16; ++it) {          // stage A (gathered emb rows)
            int idx = tid + it * 256;
            int kk = idx & 31, r = idx >> 5;
            int k = k0 + kk;
            Asm[r*34 + kk] = (k < En) ? emb[(size_t)tok[r] * En + k] : 0.f;
        }
        #pragma unroll
        for (int it = 0; it < 8; ++it) {           // stage B (w_ih slice)
            int idx = tid + it * 256;
            int kk = idx & 31, r = idx >> 5;
            int k = k0 + kk;
            int jg = (colbase + r) & 1023;
            Bsm[r*34 + kk] = (k < En) ? wsrc[jg * En + k] : 0.f;
        }
        __syncthreads();
        #pragma unroll
        for (int kk = 0; kk < 32; kk += 2) {
            ull ap[8], bp[4];
            #pragma unroll
            for (int i = 0; i < 8; i++) ap[i] = *(const ull*)&Asm[(ty*8 + i)*34 + kk];
            #pragma unroll
            for (int j = 0; j < 4; j++) bp[j] = *(const ull*)&Bsm[(tx*4 + j)*34 + kk];
            #pragma unroll
            for (int i = 0; i < 8; i++)
                #pragma unroll
                for (int j = 0; j < 4; j++) fma2(acc[i][j], ap[i], bp[j]);
        }
        __syncthreads();
    }
    const float* bih = dir ? bihb : bihf;
    const float* bhh = dir ? bhhb : bhhf;
    float* outp = g_xproj[dir];
    #pragma unroll
    for (int i = 0; i < 8; i++) {
        int row = rowbase + ty*8 + i;
        #pragma unroll
        for (int j = 0; j < 4; j++) {
            int jg = (colbase + tx*4 + j) & 1023;
            outp[(size_t)row * G4 + jg] = hadd2(acc[i][j]) + bih[jg] + bhh[jg];
        }
    }
}

// ---------------- kernel 2: BiLSTM recurrence + masked pooled sum ----------------
// 128 blocks = dir(2) x bq(4) x ubk(16). 256 threads = bl(16) x ul(16).
// Each thread owns one (b, u): 4 gate dot-products of length 256 per step.
// h in smem b-major [16][260] (pad => conflict-free LDS.128), w in smem [64][260].
__global__ void __launch_bounds__(256,1) recur_kernel(
    const float* __restrict__ whh_f, const float* __restrict__ whh_b,
    const int* __restrict__ text_len)
{
    extern __shared__ __align__(16) float dyn[];
    float* h_sm = dyn;               // 16*260 floats
    float* w_sm = dyn + 16*260;      // 64*260 floats: row = ul*4+g

    int bx  = blockIdx.x;
    int dir = bx >> 6;
    int rr  = bx & 63;
    int bq  = rr >> 4;               // batch quarter 0..3
    int ubk = rr & 15;               // unit block 0..15
    int tid = threadIdx.x;
    int bl = tid & 15, ul = tid >> 4;
    int b = bq*16 + bl;
    int u = ubk*16 + ul;

    const float* whh = dir ? whh_b : whh_f;
    #pragma unroll 4
    for (int row = 0; row < 64; ++row) {          // stage w_hh slice (once)
        int ul2 = row >> 2, g = row & 3;
        w_sm[row*260 + tid] = whh[(size_t)(g*Hn + ubk*16 + ul2) * Hn + tid];
    }
    __syncthreads();

    unsigned hb_addr = (unsigned)__cvta_generic_to_shared(h_sm + bl*260);
    unsigned wb_addr = (unsigned)__cvta_generic_to_shared(w_sm + (ul*4)*260);

    float c = 0.f, pooled = 0.f;
    int len = text_len[b];
    const float* xp = g_xproj[dir];

    for (int step = 0; step < Tn; ++step) {
        int tpos = dir ? (Tn - 1 - step) : step;
        const float* xr = xp + ((size_t)b*Tn + tpos)*G4 + u;
        float g0 = xr[0];
        float g1 = xr[Hn];
        float g2 = xr[2*Hn];
        float g3 = xr[3*Hn];

        if (step > 0) {
            // ---- per-dir grid barrier (64 blocks, monotonic count) ----
            __threadfence();
            __syncthreads();
            if (tid == 0) {
                atomicAdd(&g_cnt[dir], 1u);
                unsigned tgt = 64u * (unsigned)step;
                while (*(volatile unsigned*)&g_cnt[dir] < tgt) __nanosleep(32);
            }
            __syncthreads();
            // ---- copy this block's batch-quarter of h (16 x 256) into smem ----
            const float* hsrc = g_hbuf[dir][(step + 1) & 1] + (size_t)bq*16*Hn;
            #pragma unroll
            for (int j = 0; j < 4; j++) {
                int idx = tid + j*256;           // 0..1023 float4 chunks
                int row = idx >> 6, c4 = idx & 63;
                float4 v = __ldcg((const float4*)(hsrc + row*Hn + c4*4));
                *(float4*)&h_sm[row*260 + c4*4] = v;
            }
            __syncthreads();
            // ---- gate dot products, packed f32x2 ----
            ull a0=0,a1=0,a2=0,a3=0,e0=0,e1=0,e2=0,e3=0;
            #pragma unroll 4
            for (int k0 = 0; k0 < Hn; k0 += 4) {
                ull h01, h23, w01, w23;
                ldsv2(h01, h23, hb_addr + k0*4);
                ldsv2(w01, w23, wb_addr + k0*4);          fma2(a0,w01,h01); fma2(e0,w23,h23);
                ldsv2(w01, w23, wb_addr + 1040 + k0*4);   fma2(a1,w01,h01); fma2(e1,w23,h23);
                ldsv2(w01, w23, wb_addr + 2080 + k0*4);   fma2(a2,w01,h01); fma2(e2,w23,h23);
                ldsv2(w01, w23, wb_addr + 3120 + k0*4);   fma2(a3,w01,h01); fma2(e3,w23,h23);
            }
            g0 += hadd2(a0) + hadd2(e0);
            g1 += hadd2(a1) + hadd2(e1);
            g2 += hadd2(a2) + hadd2(e2);
            g3 += hadd2(a3) + hadd2(e3);
        }
        float ig = 1.f / (1.f + __expf(-g0));
        float fg = 1.f / (1.f + __expf(-g1));
        float gg = tanhf(g2);
        float og = 1.f / (1.f + __expf(-g3));
        c = fg * c + ig * gg;
        float h = og * tanhf(c);

        g_hbuf[dir][step & 1][b*Hn + u] = h;
        if (tpos < len) pooled += h;
    }
    g_pooled[b*G2 + dir*Hn + u] = pooled;
}

// ---------------- kernel 3: fused FC head ----------------
__device__ __forceinline__ void fc_layer(
    const float* __restrict__ x, float* __restrict__ y,
    const float* __restrict__ W, const float* __restrict__ bias, float bscale,
    int K, int N, int dorelu, int lane, int warp)
{
    for (int j0 = warp*8; j0 < N; j0 += 64) {
        float acc[8];
        #pragma unroll
        for (int jj = 0; jj < 8; jj++) acc[jj] = 0.f;
        for (int k = lane; k < K; k += 32) {
            float xv = x[k];
            #pragma unroll
            for (int jj = 0; jj < 8; jj++)
                acc[jj] += W[(j0 + jj)*K + k] * xv;
        }
        #pragma unroll
        for (int jj = 0; jj < 8; jj++)
            #pragma unroll
            for (int off = 16; off; off >>= 1)
                acc[jj] += __shfl_xor_sync(0xffffffffu, acc[jj], off);
        if (lane == 0) {
            #pragma unroll
            for (int jj = 0; jj < 8; jj++) {
                float v = acc[jj] + bias[j0 + jj] * bscale;
                y[j0 + jj] = dorelu ? fmaxf(v, 0.f) : v;
            }
        }
    }
}

__global__ void __launch_bounds__(256) head_kernel(
    const float* __restrict__ gatw, const float* __restrict__ gatb,
    const float* __restrict__ fc1w, const float* __restrict__ fc1b,
    const float* __restrict__ fc2w, const float* __restrict__ fc2b,
    const float* __restrict__ fcfw, const float* __restrict__ fcfb,
    const int* __restrict__ text_len, float* __restrict__ out)
{
    __shared__ float xa[512];
    __shared__ float xb[512];
    int bsel = blockIdx.x;
    int tid = threadIdx.x;
    int lane = tid & 31, warp = tid >> 5;
    for (int k = tid; k < 512; k += 256) xa[k] = g_pooled[bsel*512 + k];
    __syncthreads();
    float lenf = (float)text_len[bsel];

    fc_layer(xa, xb, gatw, gatb, lenf, 512, 512, 1, lane, warp);   // GAT sum head
    __syncthreads();
    fc_layer(xb, xa, fc1w, fc1b, 1.f, 512, 256, 1, lane, warp);    // fc1
    __syncthreads();
    fc_layer(xa, xb, fc2w, fc2b, 1.f, 256, 256, 1, lane, warp);    // fc2
    __syncthreads();
    if (warp == 0) {                                               // final 256 -> 2
        #pragma unroll
        for (int j = 0; j < 2; j++) {
            float acc = 0.f;
            for (int k = lane; k < 256; k += 32) acc += fcfw[j*256 + k] * xb[k];
            #pragma unroll
            for (int off = 16; off; off >>= 1)
                acc += __shfl_xor_sync(0xffffffffu, acc, off);
            if (lane == 0) out[bsel*2 + j] = acc + fcfb[j];
        }
    }
}

// ---------------- host entry ----------------
extern "C" void kernel_launch(void* const* d_in, const int* in_sizes, int n_in,
                              void* d_out, int out_size)
{
    const int*   sentence = (const int*)d_in[0];
    const int*   text_len = (const int*)d_in[4];
    const float* emb  = (const float*)d_in[10];
    const float* wihf = (const float*)d_in[11];
    const float* whhf = (const float*)d_in[12];
    const float* bihf = (const float*)d_in[13];
    const float* bhhf = (const float*)d_in[14];
    const float* wihb = (const float*)d_in[15];
    const float* whhb = (const float*)d_in[16];
    const float* bihb = (const float*)d_in[17];
    const float* bhhb = (const float*)d_in[18];
    const float* gatw = (const float*)d_in[19];
    const float* gatb = (const float*)d_in[20];
    const float* fc1w = (const float*)d_in[21];
    const float* fc1b = (const float*)d_in[22];
    const float* fc2w = (const float*)d_in[23];
    const float* fc2b = (const float*)d_in[24];
    const float* fcfw = (const float*)d_in[25];
    const float* fcfb = (const float*)d_in[26];
    float* out = (float*)d_out;

    const int dynsz = (16*260 + 64*260) * 4;   // 83200 B
    cudaFuncSetAttribute(recur_kernel, cudaFuncAttributeMaxDynamicSharedMemorySize, dynsz);

    proj_kernel<<<dim3(32, 64), 256>>>(sentence, emb, wihf, wihb, bihf, bhhf, bihb, bhhb);
    reset_kernel<<<1, 32>>>();
    recur_kernel<<<128, 256, dynsz>>>(whhf, whhb, text_len);
    head_kernel<<<64, 256>>>(gatw, gatb, fc1w, fc1b, fc2w, fc2b, fcfw, fcfb, text_len, out);
}

// round 3
// speedup vs baseline: 1.6778x; 1.2812x over previous
#include <cuda_runtime.h>
#include <math.h>

typedef unsigned long long ull;

#define Bn  64
#define Tn  128
#define En  300
#define Hn  256
#define G4  1024
#define G2  512

// ---------------- device scratch ----------------
__device__ float g_xproj[2][(size_t)Bn*Tn*G4];   // [dir][(b*T+t)*1024 + u*4 + gate]
__device__ float g_hbuf[2][2][Bn*Hn];            // [dir][parity][b*256 + u]
__device__ float g_pooled[Bn*G2];
__device__ float g_act0[Bn*G2];
__device__ float g_act1[Bn*G2];
__device__ unsigned g_cnt[2];

// ---------------- packed f32x2 helpers ----------------
__device__ __forceinline__ void fma2(ull& d, ull a, ull b){
    asm("fma.rn.f32x2 %0, %1, %2, %0;" : "+l"(d) : "l"(a), "l"(b));
}
__device__ __forceinline__ float hadd2(ull v){
    float a, b;
    asm("mov.b64 {%0, %1}, %2;" : "=f"(a), "=f"(b) : "l"(v));
    return a + b;
}
__device__ __forceinline__ ull pack2(float lo, float hi){
    ull r;
    asm("mov.b64 %0, {%1, %2};" : "=l"(r) : "f"(lo), "f"(hi));
    return r;
}
__device__ __forceinline__ void unpack2(float& lo, float& hi, ull v){
    asm("mov.b64 {%0, %1}, %2;" : "=f"(lo), "=f"(hi) : "l"(v));
}
__device__ __forceinline__ void ldsv2(ull& a, ull& b, unsigned addr){
    asm volatile("ld.shared.v2.b64 {%0, %1}, [%2];" : "=l"(a), "=l"(b) : "r"(addr));
}

// ---------------- kernel 0: barrier reset ----------------
__global__ void reset_kernel(){
    if (threadIdx.x < 2) g_cnt[threadIdx.x] = 0u;
}

// ---------------- kernel 1: gathered input projection GEMM ----------------
// Tile: 128 rows x 128 cols, K chunks of 32, micro 8x8 per thread.
// A (emb rows) and B (w_ih rows) staged k-major with stride 130.
// acc paired over ROW pairs (i,2i+1) -> no horizontal add; B scalar broadcast.
// Output gate-interleaved: xproj[row*1024 + u*4 + gate].
__global__ void __launch_bounds__(256,2) proj_kernel(
    const int* __restrict__ sentence, const float* __restrict__ emb,
    const float* __restrict__ wf, const float* __restrict__ wb,
    const float* __restrict__ bihf, const float* __restrict__ bhhf,
    const float* __restrict__ bihb, const float* __restrict__ bhhb)
{
    __shared__ __align__(16) float Asm[32*130];
    __shared__ __align__(16) float Bsm[32*130];
    __shared__ int tok[128];
    int tid = threadIdx.x;
    int rowbase = blockIdx.y * 128;
    int colbase = blockIdx.x * 128;         // 0..2047; dir uniform per block
    int dir = colbase >> 10;
    const float* wsrc = dir ? wb : wf;
    if (tid < 128) tok[tid] = sentence[rowbase + tid];
    __syncthreads();

    int tx = tid & 15, ty = tid >> 4;       // tx: 16 j-lanes, ty: 16 row-groups
    ull acc[4][8];                           // [row-pair][j: tx+16*m]
    #pragma unroll
    for (int i = 0; i < 4; i++)
        #pragma unroll
        for (int m = 0; m < 8; m++) acc[i][m] = 0ull;

    for (int k0 = 0; k0 < 320; k0 += 32) {
        #pragma unroll
        for (int it = 0; it < 16; ++it) {           // stage A: [kk][row]
            int idx = tid + it * 256;
            int kk = idx & 31, r = idx >> 5;
            int k = k0 + kk;
            Asm[kk*130 + r] = (k < En) ? emb[(size_t)tok[r] * En + k] : 0.f;
        }
        #pragma unroll
        for (int it = 0; it < 16; ++it) {           // stage B: [kk][j]
            int idx = tid + it * 256;
            int kk = idx & 31, j = idx >> 5;
            int k = k0 + kk;
            int jg = (colbase + j) & 1023;
            Bsm[kk*130 + j] = (k < En) ? wsrc[jg * En + k] : 0.f;
        }
        __syncthreads();
        #pragma unroll 4
        for (int kk = 0; kk < 32; ++kk) {
            const float* arow = &Asm[kk*130 + ty*8];
            const float* brow = &Bsm[kk*130 + tx];
            ull ap[4];
            #pragma unroll
            for (int i = 0; i < 4; i++) ap[i] = *(const ull*)(arow + 2*i);
            #pragma unroll
            for (int m = 0; m < 8; m++) {
                float bv = brow[m*16];
                ull bb = pack2(bv, bv);
                #pragma unroll
                for (int i = 0; i < 4; i++) fma2(acc[i][m], ap[i], bb);
            }
        }
        __syncthreads();
    }
    const float* bih = dir ? bihb : bihf;
    const float* bhh = dir ? bhhb : bhhf;
    float* outp = g_xproj[dir];
    #pragma unroll
    for (int m = 0; m < 8; m++) {
        int jg = (colbase + tx + m*16) & 1023;
        int u = jg & 255, g = jg >> 8;
        float bsum = bih[jg] + bhh[jg];
        #pragma unroll
        for (int i = 0; i < 4; i++) {
            float lo, hi;
            unpack2(lo, hi, acc[i][m]);
            int r0 = rowbase + ty*8 + 2*i;
            outp[(size_t)r0 * G4 + u*4 + g]       = lo + bsum;
            outp[(size_t)(r0+1) * G4 + u*4 + g]   = hi + bsum;
        }
    }
}

// ---------------- kernel 2: BiLSTM recurrence + masked pooled sum ----------------
// 128 blocks = dir(2) x bq(4) x ubk(16). 256 threads = bl(16) x ul(16).
// Per-dir grid barrier: red.release + ld.acquire poll (no membar, no nanosleep).
__global__ void __launch_bounds__(256,1) recur_kernel(
    const float* __restrict__ whh_f, const float* __restrict__ whh_b,
    const int* __restrict__ text_len)
{
    extern __shared__ __align__(16) float dyn[];
    float* h_sm = dyn;               // 16*260
    float* w_sm = dyn + 16*260;      // 64*260: row = ul*4+g

    int bx  = blockIdx.x;
    int dir = bx >> 6;
    int rr  = bx & 63;
    int bq  = rr >> 4;
    int ubk = rr & 15;
    int tid = threadIdx.x;
    int bl = tid & 15, ul = tid >> 4;
    int b = bq*16 + bl;
    int u = ubk*16 + ul;

    const float* whh = dir ? whh_b : whh_f;
    #pragma unroll 4
    for (int row = 0; row < 64; ++row) {
        int ul2 = row >> 2, g = row & 3;
        w_sm[row*260 + tid] = whh[(size_t)(g*Hn + ubk*16 + ul2) * Hn + tid];
    }
    __syncthreads();

    unsigned hb_addr = (unsigned)__cvta_generic_to_shared(h_sm + bl*260);
    unsigned wb_addr = (unsigned)__cvta_generic_to_shared(w_sm + (ul*4)*260);

    float c = 0.f, pooled = 0.f;
    int len = text_len[b];
    const float* xp = g_xproj[dir];
    unsigned* cnt = &g_cnt[dir];

    for (int step = 0; step < Tn; ++step) {
        int tpos = dir ? (Tn - 1 - step) : step;
        float4 gx = *(const float4*)(xp + ((size_t)b*Tn + tpos)*G4 + u*4);
        float g0 = gx.x, g1 = gx.y, g2 = gx.z, g3 = gx.w;

        if (step > 0) {
            // ---- per-dir grid barrier ----
            __syncthreads();
            if (tid == 0) {
                unsigned tgt = 64u * (unsigned)step;
                asm volatile("red.release.gpu.global.add.u32 [%0], 1;"
                             :: "l"(cnt) : "memory");
                unsigned v;
                do {
                    asm volatile("ld.acquire.gpu.global.u32 %0, [%1];"
                                 : "=r"(v) : "l"(cnt) : "memory");
                } while (v < tgt);
            }
            __syncthreads();
            // ---- copy this block's batch-quarter of h (16 x 256) into smem ----
            const float* hsrc = g_hbuf[dir][(step + 1) & 1] + (size_t)bq*16*Hn;
            #pragma unroll
            for (int j = 0; j < 4; j++) {
                int idx = tid + j*256;
                int row = idx >> 6, c4 = idx & 63;
                float4 v = __ldcg((const float4*)(hsrc + row*Hn + c4*4));
                *(float4*)&h_sm[row*260 + c4*4] = v;
            }
            __syncthreads();
            // ---- gate dot products, packed f32x2 ----
            ull a0=0,a1=0,a2=0,a3=0,e0=0,e1=0,e2=0,e3=0;
            #pragma unroll 4
            for (int k0 = 0; k0 < Hn; k0 += 4) {
                ull h01, h23, w01, w23;
                ldsv2(h01, h23, hb_addr + k0*4);
                ldsv2(w01, w23, wb_addr + k0*4);          fma2(a0,w01,h01); fma2(e0,w23,h23);
                ldsv2(w01, w23, wb_addr + 1040 + k0*4);   fma2(a1,w01,h01); fma2(e1,w23,h23);
                ldsv2(w01, w23, wb_addr + 2080 + k0*4);   fma2(a2,w01,h01); fma2(e2,w23,h23);
                ldsv2(w01, w23, wb_addr + 3120 + k0*4);   fma2(a3,w01,h01); fma2(e3,w23,h23);
            }
            g0 += hadd2(a0) + hadd2(e0);
            g1 += hadd2(a1) + hadd2(e1);
            g2 += hadd2(a2) + hadd2(e2);
            g3 += hadd2(a3) + hadd2(e3);
        }
        float ig = 1.f / (1.f + __expf(-g0));
        float fg = 1.f / (1.f + __expf(-g1));
        float gg = tanhf(g2);
        float og = 1.f / (1.f + __expf(-g3));
        c = fg * c + ig * gg;
        float h = og * tanhf(c);

        g_hbuf[dir][step & 1][b*Hn + u] = h;
        if (tpos < len) pooled += h;
    }
    g_pooled[b*G2 + dir*Hn + u] = pooled;
}

// ---------------- kernel 3: FC layer GEMM ----------------
// Block tile: all 64 b x 16 j, full K. X (64 x K) + W (16 x K) staged in smem.
// Thread (bl,jl): 4 batches x 1 output, k-paired f32x2, no cross-thread reduce.
// K must be a power of two (512 or 256); kshift = log2(K).
__global__ void __launch_bounds__(256,1) fc_kernel(
    const float* __restrict__ X, const float* __restrict__ W,
    const float* __restrict__ bias, const int* __restrict__ lenp,
    float* __restrict__ out, int K, int kshift, int N, int dorelu)
{
    extern __shared__ __align__(16) float fsm[];
    int KP = K + 2;
    float* Xs = fsm;            // 64 * KP
    float* Ws = fsm + 64*KP;    // 16 * KP
    int tid = threadIdx.x;
    int jt = blockIdx.x;

    for (int i = tid; i < 64*K; i += 256) {
        int b = i >> kshift, k = i & (K-1);
        Xs[b*KP + k] = X[i];
    }
    for (int i = tid; i < 16*K; i += 256) {
        int jl = i >> kshift, k = i & (K-1);
        int j = jt*16 + jl;
        Ws[jl*KP + k] = (j < N) ? W[(size_t)j*K + k] : 0.f;
    }
    __syncthreads();

    int bl = tid & 15, jl = tid >> 4;
    int j = jt*16 + jl;
    if (j >= N) return;

    ull acc[4];
    #pragma unroll
    for (int q = 0; q < 4; q++) acc[q] = 0ull;
    const float* wrow = &Ws[jl*KP];
    #pragma unroll 4
    for (int k = 0; k < K; k += 2) {
        ull wp = *(const ull*)(wrow + k);
        #pragma unroll
        for (int q = 0; q < 4; q++) {
            ull xpr = *(const ull*)(&Xs[(bl + 16*q)*KP + k]);
            fma2(acc[q], xpr, wp);
        }
    }
    #pragma unroll
    for (int q = 0; q < 4; q++) {
        int b = bl + 16*q;
        float bscale = lenp ? (float)lenp[b] : 1.f;
        float v = hadd2(acc[q]) + bias[j] * bscale;
        if (dorelu) v = fmaxf(v, 0.f);
        out[b*N + j] = v;
    }
}

// ---------------- host entry ----------------
extern "C" void kernel_launch(void* const* d_in, const int* in_sizes, int n_in,
                              void* d_out, int out_size)
{
    const int*   sentence = (const int*)d_in[0];
    const int*   text_len = (const int*)d_in[4];
    const float* emb  = (const float*)d_in[10];
    const float* wihf = (const float*)d_in[11];
    const float* whhf = (const float*)d_in[12];
    const float* bihf = (const float*)d_in[13];
    const float* bhhf = (const float*)d_in[14];
    const float* wihb = (const float*)d_in[15];
    const float* whhb = (const float*)d_in[16];
    const float* bihb = (const float*)d_in[17];
    const float* bhhb = (const float*)d_in[18];
    const float* gatw = (const float*)d_in[19];
    const float* gatb = (const float*)d_in[20];
    const float* fc1w = (const float*)d_in[21];
    const float* fc1b = (const float*)d_in[22];
    const float* fc2w = (const float*)d_in[23];
    const float* fc2b = (const float*)d_in[24];
    const float* fcfw = (const float*)d_in[25];
    const float* fcfb = (const float*)d_in[26];
    float* out = (float*)d_out;

    const int recur_smem = (16*260 + 64*260) * 4;
    cudaFuncSetAttribute(recur_kernel, cudaFuncAttributeMaxDynamicSharedMemorySize, recur_smem);
    const int fc_smem512 = 80 * 514 * 4;    // 164,480 B
    const int fc_smem256 = 80 * 258 * 4;    //  82,560 B
    cudaFuncSetAttribute(fc_kernel, cudaFuncAttributeMaxDynamicSharedMemorySize, fc_smem512);

    void *p_pooled, *p_a0, *p_a1;
    cudaGetSymbolAddress(&p_pooled, g_pooled);
    cudaGetSymbolAddress(&p_a0, g_act0);
    cudaGetSymbolAddress(&p_a1, g_act1);

    proj_kernel<<<dim3(16, 64), 256>>>(sentence, emb, wihf, wihb, bihf, bhhf, bihb, bhhb);
    reset_kernel<<<1, 32>>>();
    recur_kernel<<<128, 256, recur_smem>>>(whhf, whhb, text_len);
    fc_kernel<<<32, 256, fc_smem512>>>((const float*)p_pooled, gatw, gatb, text_len,
                                       (float*)p_a0, 512, 9, 512, 1);
    fc_kernel<<<16, 256, fc_smem512>>>((const float*)p_a0, fc1w, fc1b, nullptr,
                                       (float*)p_a1, 512, 9, 256, 1);
    fc_kernel<<<16, 256, fc_smem256>>>((const float*)p_a1, fc2w, fc2b, nullptr,
                                       (float*)p_a0, 256, 8, 256, 1);
    fc_kernel<<<1, 256, fc_smem256>>> ((const float*)p_a0, fcfw, fcfb, nullptr,
                                       out, 256, 8, 2, 0);
}